// round 14
// baseline (speedup 1.0000x reference)
#include <cuda_runtime.h>
#include <cstdint>

#define HID    1024
#define BATCH  32
#define LAYERS 3
#define OUTDIM 2500
#define GRID_N 50
#define MODES  32
#define TIME   64

#define GRU_MT  192         // 3072/16 m-tiles per matrix
#define GRU_KT  128         // 1024/8 k8-tiles
#define KS8     8           // K-slices per matrix (K=128 each)
#define FC_MT   160         // padded 2560/16
#define FC_KT   128
#define KS_FC   16
#define KSLICE_FC 64
#define M_FC_PAD 2512

// ---------------- persistent device state ------------------------------------
__device__ float g_h[2][LAYERS][BATCH][HID];
__device__ float g_x[BATCH][HID];
__device__ float g_ct[MODES][GRID_N];
__device__ float g_st[MODES][GRID_N];
__device__ float g_part6[6 * KS8 * 3072 * 32];        // GRU split-K partials
__device__ float g_fpart[KS_FC * 32 * M_FC_PAD];      // FC partials

// fragment-swizzled fp32 weights: [mat][mt][kt8][128]; mats 0-2 ih, 3-5 hh
__device__ float g_Wsw[(size_t)6 * GRU_MT * GRU_KT * 128];   // 75.5 MB
__device__ float g_Fsw[(size_t)FC_MT * FC_KT * 128];         // 10.5 MB

// ---------------- helpers ----------------------------------------------------
__device__ __forceinline__ uint32_t f2tf(float f) {
    uint32_t u;
    asm("cvt.rna.tf32.f32 %0, %1;" : "=r"(u) : "f"(f));
    return u;
}

__device__ __forceinline__ void mma1688(float* c,
                                        uint32_t a0, uint32_t a1, uint32_t a2, uint32_t a3,
                                        uint32_t b0, uint32_t b1) {
    asm volatile(
        "mma.sync.aligned.m16n8k8.row.col.f32.tf32.tf32.f32 "
        "{%0,%1,%2,%3}, {%4,%5,%6,%7}, {%8,%9}, {%0,%1,%2,%3};"
        : "+f"(c[0]), "+f"(c[1]), "+f"(c[2]), "+f"(c[3])
        : "r"(a0), "r"(a1), "r"(a2), "r"(a3), "r"(b0), "r"(b1));
}

__device__ __forceinline__ uint32_t smem_u32(const void* p) {
    return (uint32_t)__cvta_generic_to_shared(p);
}

__device__ __forceinline__ void cp16(uint32_t dst, const void* src) {
    asm volatile("cp.async.cg.shared.global [%0], [%1], 16;" :: "r"(dst), "l"(src));
}
__device__ __forceinline__ void cp_commit() {
    asm volatile("cp.async.commit_group;");
}
template<int N> __device__ __forceinline__ void cp_wait() {
    asm volatile("cp.async.wait_group %0;" :: "n"(N));
}

// ---------------- init -------------------------------------------------------
__global__ void init_kernel(const float* __restrict__ x)
{
    int tid    = blockIdx.x * blockDim.x + threadIdx.x;
    int stride = gridDim.x * blockDim.x;

    float* hflat = (float*)g_h;
    for (int i = tid; i < 2 * LAYERS * BATCH * HID; i += stride) hflat[i] = 0.0f;

    float* xflat = (float*)g_x;
    for (int i = tid; i < BATCH * HID; i += stride) xflat[i] = x[i];

    for (int i = tid; i < MODES * GRID_N; i += stride) {
        int t = i / GRID_N;
        int n = i % GRID_N;
        float arg = 2.0f * (float)(t - 16) * (float)n / 50.0f;  // units of pi
        g_ct[t][n] = cospif(arg);
        g_st[t][n] = sinpif(arg);
    }
}

// ---------------- weight repack: fp32 fragment order -------------------------
__global__ void repack_gru(const float* __restrict__ W_ih,
                           const float* __restrict__ W_hh)
{
    int64_t total = (int64_t)6 * GRU_MT * GRU_KT * 128;
    for (int64_t idx = (int64_t)blockIdx.x * blockDim.x + threadIdx.x;
         idx < total; idx += (int64_t)gridDim.x * blockDim.x) {
        int within = (int)(idx & 127);
        int e    = within & 3;
        int lane = within >> 2;
        int kt   = (int)((idx >> 7) & (GRU_KT - 1));
        int tmp  = (int)(idx >> 14);           // mat*GRU_MT + mt
        int mt   = tmp % GRU_MT;
        int mat  = tmp / GRU_MT;
        int l    = mat % 3;
        const float* src = ((mat < 3) ? W_ih : W_hh) + (size_t)l * 3 * HID * HID;
        int g = lane >> 2, t = lane & 3;
        int r = mt * 16 + g + (e & 1) * 8;
        int c = kt * 8 + t + (e >> 1) * 4;
        g_Wsw[idx] = src[(size_t)r * HID + c];
    }
}

__global__ void repack_fc(const float* __restrict__ fc_w)
{
    int64_t total = (int64_t)FC_MT * FC_KT * 128;
    for (int64_t idx = (int64_t)blockIdx.x * blockDim.x + threadIdx.x;
         idx < total; idx += (int64_t)gridDim.x * blockDim.x) {
        int within = (int)(idx & 127);
        int e    = within & 3;
        int lane = within >> 2;
        int kt   = (int)((idx >> 7) & (FC_KT - 1));
        int mt   = (int)(idx >> 14);
        int g = lane >> 2, t = lane & 3;
        int r = mt * 16 + g + (e & 1) * 8;
        int c = kt * 8 + t + (e >> 1) * 4;
        g_Fsw[idx] = (r < OUTDIM) ? fc_w[(size_t)r * HID + c] : 0.0f;
    }
}

// ---------------- GRU gate GEMM (split-K, 3xTF32, cp.async, raw-B, PDL) ------
// grid (48, 8, njobs). Each job = (mat, src) pair: per-job hidden-buffer parity
// so hh jobs for step t+1 can ride in step-t launches.
__global__ __launch_bounds__(128, 8) void gru_gemm(
    int j0, int s0, int j1, int s1, int j2, int s2)
{
    __shared__ float4 sA[2 * 4 * 2 * 32];   // [slot][warp][kt2][lane], 8 KB
    __shared__ float  vB[32 * 132];         // raw fp32 B, stride 132

    cudaGridDependencySynchronize();

    int mat, src;
    if (blockIdx.z == 0)      { mat = j0; src = s0; }
    else if (blockIdx.z == 1) { mat = j1; src = s1; }
    else                      { mat = j2; src = s2; }

    const int ks   = blockIdx.y;
    const int warp = threadIdx.x >> 5;
    const int lane = threadIdx.x & 31;
    const int g    = lane >> 2;
    const int t    = lane & 3;
    const int m0   = blockIdx.x * 64 + warp * 16;
    const int koff = ks * 128;
    const int l    = mat % 3;

    const int mt = blockIdx.x * 4 + warp;
    const float4* pA4 = (const float4*)(g_Wsw
                      + (((size_t)mat * GRU_MT + mt) * GRU_KT + ks * 16) * 128);
    const uint32_t sA_base = smem_u32(sA);
    const uint32_t vB_base = smem_u32(vB);

    // group 0: B (raw fp32, 16 KB), each thread copies 128 B of one row-quarter
    const float* bsrc = (mat >= 3) ? &g_h[src][l][0][0]
                      : (l == 0)   ? &g_x[0][0]
                                   : &g_h[src ^ 1][l - 1][0][0];
    {
        int n = threadIdx.x >> 2;
        int q = threadIdx.x & 3;
        const float* srcp = bsrc + n * HID + koff + q * 32;
        uint32_t dstp = vB_base + (n * 132 + q * 32) * 4;
        #pragma unroll
        for (int j = 0; j < 8; j++)
            cp16(dstp + j * 16, srcp + j * 4);
        cp_commit();
    }

    auto issue_chunk = [&](int c, int slot) {
        #pragma unroll
        for (int kt = 0; kt < 2; kt++) {
            uint32_t d = sA_base + ((((slot * 4 + warp) * 2 + kt) * 32 + lane) << 4);
            cp16(d, pA4 + (c * 2 + kt) * 32 + lane);
        }
        cp_commit();
    };

    issue_chunk(0, 0);
    issue_chunk(1, 1);

    cp_wait<2>();            // B complete
    __syncthreads();

    float c4[4][4] = {};

    auto process = [&](int c, int slot) {
        #pragma unroll
        for (int kt = 0; kt < 2; kt++) {
            float4 fr = sA[((slot * 4 + warp) * 2 + kt) * 32 + lane];
            int k0 = (c * 2 + kt) * 8;
            uint32_t ah0 = f2tf(fr.x), ah1 = f2tf(fr.y), ah2 = f2tf(fr.z), ah3 = f2tf(fr.w);
            uint32_t al0 = f2tf(fr.x - __uint_as_float(ah0));
            uint32_t al1 = f2tf(fr.y - __uint_as_float(ah1));
            uint32_t al2 = f2tf(fr.z - __uint_as_float(ah2));
            uint32_t al3 = f2tf(fr.w - __uint_as_float(ah3));
            #pragma unroll
            for (int nt = 0; nt < 4; nt++) {
                int n = nt * 8 + g;
                float b0 = vB[n * 132 + k0 + t];
                float b1 = vB[n * 132 + k0 + t + 4];
                uint32_t bh0 = f2tf(b0);
                uint32_t bh1 = f2tf(b1);
                uint32_t bl0 = f2tf(b0 - __uint_as_float(bh0));
                uint32_t bl1 = f2tf(b1 - __uint_as_float(bh1));
                mma1688(c4[nt], ah0, ah1, ah2, ah3, bh0, bh1);
                mma1688(c4[nt], ah0, ah1, ah2, ah3, bl0, bl1);
                mma1688(c4[nt], al0, al1, al2, al3, bh0, bh1);
            }
        }
    };

    // 8 chunks through 2 slots
    cp_wait<1>();  process(0, 0);  issue_chunk(2, 0);
    cp_wait<1>();  process(1, 1);  issue_chunk(3, 1);
    cp_wait<1>();  process(2, 0);  issue_chunk(4, 0);
    cp_wait<1>();  process(3, 1);  issue_chunk(5, 1);
    cp_wait<1>();  process(4, 0);  issue_chunk(6, 0);
    cp_wait<1>();  process(5, 1);  issue_chunk(7, 1);
    cp_wait<1>();  process(6, 0);
    cp_wait<0>();  process(7, 1);

    #pragma unroll
    for (int nt = 0; nt < 4; nt++) {
        int n = nt * 8 + 2 * t;
        float* base = g_part6 + (((size_t)mat * KS8 + ks) * 3072 + (m0 + g)) * 32 + n;
        *(float2*)base            = make_float2(c4[nt][0], c4[nt][1]);
        *(float2*)(base + 8 * 32) = make_float2(c4[nt][2], c4[nt][3]);
    }

    cudaTriggerProgrammaticLaunchCompletion();
}

// ---------------- GRU cell pointwise (PDL) -----------------------------------
__global__ __launch_bounds__(256) void gru_cell(
    int layer, int src,
    const float* __restrict__ b_ih_all,
    const float* __restrict__ b_hh_all)
{
    cudaGridDependencySynchronize();

    const int dst = src ^ 1;
    const int gid = blockIdx.x * 256 + threadIdx.x;
    const int b   = gid & 31;
    const int u   = gid >> 5;

    float i_r = 0.f, i_z = 0.f, i_n = 0.f, h_r = 0.f, h_z = 0.f, h_n = 0.f;
    #pragma unroll
    for (int ks = 0; ks < KS8; ks++) {
        const float* p = g_part6 + ((size_t)layer * KS8 + ks) * 3072 * 32;
        i_r += p[(u)        * 32 + b];
        i_z += p[(u + 1024) * 32 + b];
        i_n += p[(u + 2048) * 32 + b];
    }
    #pragma unroll
    for (int ks = 0; ks < KS8; ks++) {
        const float* p = g_part6 + ((size_t)(3 + layer) * KS8 + ks) * 3072 * 32;
        h_r += p[(u)        * 32 + b];
        h_z += p[(u + 1024) * 32 + b];
        h_n += p[(u + 2048) * 32 + b];
    }

    const float* bih = b_ih_all + layer * 3 * HID;
    const float* bhh = b_hh_all + layer * 3 * HID;
    i_r += bih[u];           h_r += bhh[u];
    i_z += bih[u + HID];     h_z += bhh[u + HID];
    i_n += bih[u + 2 * HID]; h_n += bhh[u + 2 * HID];

    float r = 1.0f / (1.0f + expf(-(i_r + h_r)));
    float z = 1.0f / (1.0f + expf(-(i_z + h_z)));
    float n = tanhf(i_n + r * h_n);

    float h_old = g_h[src][layer][b][u];
    g_h[dst][layer][b][u] = (1.0f - z) * n + z * h_old;

    cudaTriggerProgrammaticLaunchCompletion();
}

// ---------------- FC GEMM (split-K, 3xTF32, cp.async, raw-B, PDL) ------------
__global__ __launch_bounds__(128, 8) void fc_gemm(int src)
{
    __shared__ float4 sA[2 * 4 * 2 * 32];   // 8 KB, 2 ring slots of 2 k8-tiles
    __shared__ float  vB[32 * 76];

    cudaGridDependencySynchronize();

    const int dst  = src ^ 1;
    const int ks   = blockIdx.y;
    const int warp = threadIdx.x >> 5;
    const int lane = threadIdx.x & 31;
    const int g    = lane >> 2;
    const int t    = lane & 3;
    const int m0   = blockIdx.x * 64 + warp * 16;
    const int koff = ks * KSLICE_FC;

    const int mt = blockIdx.x * 4 + warp;
    const float4* pA4 = (const float4*)(g_Fsw
                      + (((size_t)mt) * FC_KT + ks * 8) * 128);
    const uint32_t sA_base = smem_u32(sA);
    const uint32_t vB_base = smem_u32(vB);

    // group 0: B raw fp32 (8 KB)
    const float* bsrc = &g_h[dst][LAYERS - 1][0][0];
    {
        int n = threadIdx.x >> 2;
        int q = threadIdx.x & 3;
        const float* srcp = bsrc + n * HID + koff + q * 16;
        uint32_t dstp = vB_base + (n * 76 + q * 16) * 4;
        #pragma unroll
        for (int j = 0; j < 4; j++)
            cp16(dstp + j * 16, srcp + j * 4);
        cp_commit();
    }

    auto issue_chunk = [&](int c, int slot) {
        #pragma unroll
        for (int kt = 0; kt < 2; kt++) {
            uint32_t d = sA_base + ((((slot * 4 + warp) * 2 + kt) * 32 + lane) << 4);
            cp16(d, pA4 + (c * 2 + kt) * 32 + lane);
        }
        cp_commit();
    };

    issue_chunk(0, 0);
    issue_chunk(1, 1);

    cp_wait<2>();
    __syncthreads();

    float c4[4][4] = {};

    auto process = [&](int c, int slot) {
        #pragma unroll
        for (int kt = 0; kt < 2; kt++) {
            float4 fr = sA[((slot * 4 + warp) * 2 + kt) * 32 + lane];
            int k0 = (c * 2 + kt) * 8;
            uint32_t ah0 = f2tf(fr.x), ah1 = f2tf(fr.y), ah2 = f2tf(fr.z), ah3 = f2tf(fr.w);
            uint32_t al0 = f2tf(fr.x - __uint_as_float(ah0));
            uint32_t al1 = f2tf(fr.y - __uint_as_float(ah1));
            uint32_t al2 = f2tf(fr.z - __uint_as_float(ah2));
            uint32_t al3 = f2tf(fr.w - __uint_as_float(ah3));
            #pragma unroll
            for (int nt = 0; nt < 4; nt++) {
                int n = nt * 8 + g;
                float b0 = vB[n * 76 + k0 + t];
                float b1 = vB[n * 76 + k0 + t + 4];
                uint32_t bh0 = f2tf(b0);
                uint32_t bh1 = f2tf(b1);
                uint32_t bl0 = f2tf(b0 - __uint_as_float(bh0));
                uint32_t bl1 = f2tf(b1 - __uint_as_float(bh1));
                mma1688(c4[nt], ah0, ah1, ah2, ah3, bh0, bh1);
                mma1688(c4[nt], ah0, ah1, ah2, ah3, bl0, bl1);
                mma1688(c4[nt], al0, al1, al2, al3, bh0, bh1);
            }
        }
    };

    cp_wait<1>();  process(0, 0);  issue_chunk(2, 0);
    cp_wait<1>();  process(1, 1);  issue_chunk(3, 1);
    cp_wait<1>();  process(2, 0);
    cp_wait<0>();  process(3, 1);

    #pragma unroll
    for (int nt = 0; nt < 4; nt++) {
        #pragma unroll
        for (int j = 0; j < 4; j++) {
            int n = nt * 8 + 2 * t + (j & 1);
            int m = m0 + g + ((j >> 1) * 8);
            if (m < OUTDIM)
                g_fpart[((size_t)ks * 32 + n) * M_FC_PAD + m] = c4[nt][j];
        }
    }

    cudaTriggerProgrammaticLaunchCompletion();
}

// ---------------- spectral crop: FC reduce+bias, DFT, feedback (PDL) ---------
__global__ __launch_bounds__(512) void spectral_kernel(
    const float* __restrict__ fc_b, float* __restrict__ outp)
{
    const int b = blockIdx.x;
    __shared__ float a[OUTDIM];
    __shared__ float cre[GRID_N * MODES];
    __shared__ float cim[GRID_N * MODES];

    cudaGridDependencySynchronize();

    for (int i = threadIdx.x; i < OUTDIM; i += blockDim.x) {
        float s = fc_b[i];
        #pragma unroll
        for (int ks = 0; ks < KS_FC; ks++)
            s += g_fpart[((size_t)ks * 32 + b) * M_FC_PAD + i];
        a[i] = s;
        outp[b * OUTDIM + i] = s;
    }
    __syncthreads();

    for (int i = threadIdx.x; i < GRID_N * MODES; i += blockDim.x) {
        int m = i / MODES;
        int q = i % MODES;
        float sre = 0.f, sim = 0.f;
        #pragma unroll 5
        for (int n = 0; n < GRID_N; n++) {
            float v = a[m * GRID_N + n];
            sre += v * g_ct[q][n];
            sim -= v * g_st[q][n];
        }
        cre[m * MODES + q] = sre;
        cim[m * MODES + q] = sim;
    }
    __syncthreads();

    for (int i = threadIdx.x; i < MODES * MODES; i += blockDim.x) {
        int p = i / MODES;
        int q = i % MODES;
        float s = 0.f;
        #pragma unroll 5
        for (int m = 0; m < GRID_N; m++)
            s += g_ct[p][m] * cre[m * MODES + q] + g_st[p][m] * cim[m * MODES + q];
        g_x[b][i] = s;
    }

    cudaTriggerProgrammaticLaunchCompletion();
}

// ---------------- driver -----------------------------------------------------
template <typename K, typename... Args>
static inline void launch_pdl(dim3 grid, dim3 block, K kern, Args... args)
{
    cudaLaunchConfig_t cfg = {};
    cfg.gridDim = grid;
    cfg.blockDim = block;
    cfg.dynamicSmemBytes = 0;
    cfg.stream = 0;
    cudaLaunchAttribute attr[1];
    attr[0].id = cudaLaunchAttributeProgrammaticStreamSerialization;
    attr[0].val.programmaticStreamSerializationAllowed = 1;
    cfg.attrs = attr;
    cfg.numAttrs = 1;
    cudaLaunchKernelEx(&cfg, kern, args...);
}

extern "C" void kernel_launch(void* const* d_in, const int* in_sizes, int n_in,
                              void* d_out, int out_size)
{
    const float* x     = (const float*)d_in[0];
    const float* W_ih  = (const float*)d_in[1];
    const float* W_hh  = (const float*)d_in[2];
    const float* b_ih  = (const float*)d_in[3];
    const float* b_hh  = (const float*)d_in[4];
    const float* fc_w  = (const float*)d_in[5];
    const float* fc_b  = (const float*)d_in[6];
    float*       out   = (float*)d_out;

    init_kernel<<<64, 256>>>(x);
    repack_gru<<<592, 256>>>(W_ih, W_hh);
    repack_fc<<<128, 256>>>(fc_w);

    // prologue: hh0(0), hh1(0) against zeroed h (hh2(0) rides in L_A of t=0)
    launch_pdl(dim3(48, 8, 2), dim3(128), gru_gemm, 3, 0, 4, 0, 0, 0);

    for (int t = 0; t < TIME; t++) {
        int src  = t & 1;
        int srcn = src ^ 1;            // parity for step t+1 hh jobs
        float* outp = out + (size_t)t * BATCH * OUTDIM;
        bool last = (t == TIME - 1);

        // L_A: ih0(t) + hh2(t)
        launch_pdl(dim3(48, 8, 2), dim3(128), gru_gemm, 0, src, 5, src, 0, 0);
        launch_pdl(dim3(128), dim3(256), gru_cell, 0, src, b_ih, b_hh);
        // L_B: ih1(t) + hh0(t+1)  (skip hh on last step)
        launch_pdl(dim3(48, 8, last ? 1 : 2), dim3(128), gru_gemm,
                   1, src, 3, srcn, 0, 0);
        launch_pdl(dim3(128), dim3(256), gru_cell, 1, src, b_ih, b_hh);
        // L_C: ih2(t) + hh1(t+1)
        launch_pdl(dim3(48, 8, last ? 1 : 2), dim3(128), gru_gemm,
                   2, src, 4, srcn, 0, 0);
        launch_pdl(dim3(128), dim3(256), gru_cell, 2, src, b_ih, b_hh);
        launch_pdl(dim3(40, KS_FC), dim3(128), fc_gemm, src);
        launch_pdl(dim3(BATCH), dim3(512), spectral_kernel, fc_b, outp);
    }
}